// round 3
// baseline (speedup 1.0000x reference)
#include <cuda_runtime.h>

// JeffressLinear: T=64, N=16, C=256, D_OUT=129, decay = exp(-1/2)
// out[t,n,c,d] = w * sum_ch LIF( circshift(input[:,n,c,ch], dly(n,c,d,ch)) )[t]
// dly = min( stoch_round(relu(+/-delay_param[d]), u), 63 - argmax_t input[:,n,c,ch] )
// Effective dly is always in [0,63] -> precompute F[ch][t][dly] per (n,c) block.

#define T_   64
#define N_   16
#define C_   256
#define D_   129
#define DECAYF 0.60653065971263342f   // exp(-0.5)

__global__ __launch_bounds__(256, 1) void jeffress_kernel(
    const float* __restrict__ input,        // (T, N, C, 2)
    const float* __restrict__ delay_param,  // (D, 1)
    const float* __restrict__ weight,       // scalar
    const float* __restrict__ u,            // (N, C, D, 2)
    float* __restrict__ out)                // (T, N, C, D)
{
    __shared__ float xs[2][T_];          // input time series for this (n,c), per ch
    __shared__ float F[2][T_][64];       // [ch][t][dly] filtered shifted series (32 KB)
    __shared__ int   r0s[D_], r1s[D_];   // stochastically-rounded delay per d (unclamped)
    __shared__ int   Ls[2];              // 63 - spike_t per ch
    __shared__ float wsh;

    const int tid = threadIdx.x;
    const int c = blockIdx.x;
    const int n = blockIdx.y;
    const int nc = n * C_ + c;

    // ---- Phase 1: load input row, precompute rounded delays, load weight ----
    if (tid < T_) {
        const float2 v = *reinterpret_cast<const float2*>(
            input + ((size_t)(tid * N_ + n) * C_ + c) * 2);
        xs[0][tid] = v.x;
        xs[1][tid] = v.y;
    } else if (tid < 64 + D_) {
        const int d = tid - 64;
        const float dp = delay_param[d];
        const float d0 = fmaxf(dp, 0.0f);
        const float d1 = fmaxf(-dp, 0.0f);
        const float f0 = floorf(d0);
        const float f1 = floorf(d1);
        const float2 uv = reinterpret_cast<const float2*>(u)[(size_t)nc * D_ + d];
        r0s[d] = (int)f0 + ((uv.x < d0 - f0) ? 1 : 0);
        r1s[d] = (int)f1 + ((uv.y < d1 - f1) ? 1 : 0);
    } else if (tid == 224) {
        wsh = *weight;
    }
    __syncthreads();

    // ---- Phase 2: LIF recurrence for every (ch, dly); argmax on 2 spare threads ----
    if (tid < 128) {
        const int ch  = tid >> 6;
        const int dly = tid & 63;
        const float* x = xs[ch];
        float v = 0.0f;
#pragma unroll
        for (int t = 0; t < T_; ++t) {
            v = v * DECAYF + x[(t - dly) & 63];   // circular shift + leaky integrate
            F[ch][t][dly] = v;
        }
    } else if (tid < 130) {
        const int ch = tid - 128;
        float best = xs[ch][0];
        int bi = 0;
#pragma unroll
        for (int t = 1; t < T_; ++t) {
            const float val = xs[ch][t];
            if (val > best) { best = val; bi = t; }   // first max (argmax semantics)
        }
        Ls[ch] = (T_ - 1) - bi;
    }
    __syncthreads();

    // ---- Phase 3: gather + write 64x129 outputs (write-bandwidth bound) ----
    const int L0 = Ls[0];
    const int L1 = Ls[1];
    const float w = wsh;
    float* outb = out + (size_t)nc * D_;

#pragma unroll 4
    for (int i = tid; i < T_ * D_; i += 256) {
        const unsigned t = (unsigned)i / D_;
        const unsigned d = (unsigned)i - t * D_;
        const int dly0 = min(r0s[d], L0);
        const int dly1 = min(r1s[d], L1);
        const float o = (F[0][t][dly0] + F[1][t][dly1]) * w;
        outb[(size_t)t * (N_ * C_ * D_) + d] = o;
    }
}

extern "C" void kernel_launch(void* const* d_in, const int* in_sizes, int n_in,
                              void* d_out, int out_size) {
    const float* input       = (const float*)d_in[0];
    const float* delay_param = (const float*)d_in[1];
    const float* weight      = (const float*)d_in[2];
    const float* u           = (const float*)d_in[3];
    float* out = (float*)d_out;

    dim3 grid(C_, N_);
    jeffress_kernel<<<grid, 256>>>(input, delay_param, weight, u, out);
}

// round 4
// speedup vs baseline: 2.2066x; 2.2066x over previous
#include <cuda_runtime.h>
#include <stdint.h>

// JeffressLinear: T=64, N=16, C=256, D=129, decay=exp(-1/2)
// Per output column (n,c,d): s_t = s_{t-1}*decay + w*(x0[(t-dly0)&63] + x1[(t-dly1)&63])
// dly_ch = min( stoch_round(relu(+/-delay_param[d])), 63 - argmax_t x_ch ) in [0,63].
//
// Block owns G=8 consecutive nc. Output slab per t = 1032 contiguous floats
// (16B aligned, = 258 float4). 258 threads each run 4 interleaved recurrences
// and emit one STG.128 per t. Input series stored in smem pre-multiplied by w,
// doubled (i in [0,128), value x[i&63]) and TRANSPOSED-BY-4:
//   word(i) = (i&3)*32 + (i>>2), series pitch 132 words.
// Lanes (d stride 4 -> i stride 4) then hit word-stride-1 -> conflict-free,
// and i = K + t advances purely in the immediate offset when t is unrolled.

#define T_      64
#define N_      16
#define C_      256
#define D_      129
#define G_      8
#define SLAB    (G_ * D_)        // 1032
#define NV      (SLAB / 4)       // 258 vector threads
#define NT      288              // block threads (9 warps)
#define PITCH   132              // words per (g,ch) series (padded vs 128)
#define DECAYF  0.60653065971263342f
#define TSTRIDE (N_ * C_ * D_)   // 528384 floats between consecutive t planes

__global__ __launch_bounds__(NT, 4) void jeff_kernel(
    const float* __restrict__ input,        // (T, N, C, 2)
    const float* __restrict__ delay_param,  // (D, 1)
    const float* __restrict__ weight,       // scalar
    const float* __restrict__ u,            // (N, C, D, 2)
    float* __restrict__ out)                // (T, N, C, D)
{
    __shared__ float XT[2 * G_ * PITCH];              // pre-scaled, doubled, transposed series
    __shared__ __align__(16) uint32_t PK[SLAB];       // dly0 | dly1<<8 | g<<16 (unclamped)
    __shared__ int LS[2 * G_];                        // 63 - spike_t per (g,ch)

    const int tid = threadIdx.x;
    const int nc0 = blockIdx.x * G_;
    const int n   = nc0 >> 8;
    const int c0  = nc0 & 255;
    const float w = __ldg(weight);

    // ---- Phase A1: load input (coalesced: 16 consecutive floats per t), fill XT ----
    for (int j = tid; j < G_ * 2 * T_; j += NT) {
        const int t  = j >> 4;                 // consecutive lanes share t -> coalesced LDG
        const int g  = (j >> 1) & 7;
        const int ch = j & 1;
        const float v = __ldg(&input[(((size_t)t * N_ + n) * C_ + (c0 + g)) * 2 + ch]) * w;
        const int base = (g * 2 + ch) * PITCH + ((t & 3) << 5) + (t >> 2);
        XT[base]      = v;                     // i = t
        XT[base + 16] = v;                     // i = t + 64 (same r, q+16)
    }

    // ---- Phase A2: stochastic-rounded (unclamped) delays per slab position ----
    for (int j = tid; j < SLAB; j += NT) {
        const int g = (j * 8129) >> 20;        // j / 129 for j < 1032
        const int d = j - g * D_;
        const float dp = __ldg(&delay_param[d]);
        const float d0 = fmaxf(dp, 0.0f);
        const float d1 = fmaxf(-dp, 0.0f);
        const float f0 = floorf(d0);
        const float f1 = floorf(d1);
        const float2 uv = __ldg((const float2*)u + (size_t)(nc0 + g) * D_ + d);
        const int r0 = (int)f0 + ((uv.x < d0 - f0) ? 1 : 0);
        const int r1 = (int)f1 + ((uv.y < d1 - f1) ? 1 : 0);
        PK[j] = (uint32_t)r0 | ((uint32_t)r1 << 8) | ((uint32_t)g << 16);
    }
    __syncthreads();

    // ---- Phase B: first-argmax per (g,ch): 16 series x 16 lanes each ----
    if (tid < 256) {
        const int sid = tid >> 4;              // g*2 + ch
        const int l16 = tid & 15;
        const int base = sid * PITCH;
        float bv = -1.0f; int bi = 0;
#pragma unroll
        for (int k = 0; k < 4; ++k) {
            const int t = l16 * 4 + k;         // increasing t within lane; lanes ordered by t
            const float v = XT[base + ((t & 3) << 5) + (t >> 2)];
            if (v > bv) { bv = v; bi = t; }    // strict > keeps FIRST max (w > 0)
        }
#pragma unroll
        for (int off = 8; off > 0; off >>= 1) {
            const float ov = __shfl_down_sync(0xffffffffu, bv, off, 16);
            const int   oi = __shfl_down_sync(0xffffffffu, bi, off, 16);
            if (ov > bv) { bv = ov; bi = oi; } // tie -> keep lower-t (lower lane) index
        }
        if (l16 == 0) LS[sid] = 63 - bi;
    }
    __syncthreads();

    // ---- Phase C: 4 interleaved recurrences per thread, STG.128 per t ----
    if (tid < NV) {
        const uint4 pkv = *(const uint4*)&PK[tid * 4];
        const uint32_t pks[4] = { pkv.x, pkv.y, pkv.z, pkv.w };

        int A0[4][4];   // [col][j=t&3] word index for ch0, i = K0 + j
        int A1[4][4];   // ch1
#pragma unroll
        for (int c = 0; c < 4; ++c) {
            const uint32_t pk = pks[c];
            const int g    = (int)(pk >> 16);
            const int dly0 = min((int)(pk & 0xff),        LS[2 * g]);
            const int dly1 = min((int)((pk >> 8) & 0xff), LS[2 * g + 1]);
            const int K0 = 64 - dly0;                     // in [1, 64]
            const int K1 = 64 - dly1;
            const int b0 = (g * 2 + 0) * PITCH;
            const int b1 = (g * 2 + 1) * PITCH;
#pragma unroll
            for (int j = 0; j < 4; ++j) {
                const int i0 = K0 + j, i1 = K1 + j;
                A0[c][j] = b0 + ((i0 & 3) << 5) + (i0 >> 2);
                A1[c][j] = b1 + ((i1 & 3) << 5) + (i1 >> 2);
            }
        }

        float s0 = 0.f, s1 = 0.f, s2 = 0.f, s3 = 0.f;
        float* op = out + (size_t)nc0 * D_ + tid * 4;

#pragma unroll
        for (int m = 0; m < 16; ++m) {
#pragma unroll
            for (int j = 0; j < 4; ++j) {      // t = 4m + j; all LDS offsets fold to immediates
                float4 v;
                v.x = s0 = s0 * DECAYF + (XT[A0[0][j] + m] + XT[A1[0][j] + m]);
                v.y = s1 = s1 * DECAYF + (XT[A0[1][j] + m] + XT[A1[1][j] + m]);
                v.z = s2 = s2 * DECAYF + (XT[A0[2][j] + m] + XT[A1[2][j] + m]);
                v.w = s3 = s3 * DECAYF + (XT[A0[3][j] + m] + XT[A1[3][j] + m]);
                *(float4*)op = v;
                op += TSTRIDE;
            }
        }
    }
}

extern "C" void kernel_launch(void* const* d_in, const int* in_sizes, int n_in,
                              void* d_out, int out_size) {
    const float* input       = (const float*)d_in[0];
    const float* delay_param = (const float*)d_in[1];
    const float* weight      = (const float*)d_in[2];
    const float* u           = (const float*)d_in[3];
    float* out = (float*)d_out;

    jeff_kernel<<<(N_ * C_) / G_, NT>>>(input, delay_param, weight, u, out);
}